// round 3
// baseline (speedup 1.0000x reference)
#include <cuda_runtime.h>
#include <cuda_bf16.h>
#include <math.h>

// Problem constants
#define B_TOK   16384
#define D_VIS   768
#define D_LANG  768
#define D_STATE 64
#define D_IN    1600
#define D_MODEL 256
#define N_EXP   4
#define TOPK    2

typedef unsigned long long u64;

// ---------------------------------------------------------------------------
// Scratch (no runtime allocation allowed)
// ---------------------------------------------------------------------------
__device__ float g_x[B_TOK * D_MODEL];        // fused+LN+GELU activations
__device__ int   g_topidx[B_TOK];             // i0 | (i1<<8)
__device__ float g_topw[B_TOK * 2];           // w0, w1
__device__ float g_partial[2048 * 8];         // per-block [probsum x4, count x4]

__device__ __forceinline__ float gelu_exact(float v) {
    return 0.5f * v * (1.f + erff(v * 0.70710678118654752f));
}

// ---- packed fp32 helpers (sm_100+ f32x2 pipe: 2x FFMA throughput) ----------
__device__ __forceinline__ u64 pack2(float x, float y) {
    u64 r; asm("mov.b64 %0, {%1, %2};" : "=l"(r) : "f"(x), "f"(y)); return r;
}
__device__ __forceinline__ void fma2(u64& d, u64 a, u64 b) {
    asm("fma.rn.f32x2 %0, %1, %2, %0;" : "+l"(d) : "l"(a), "l"(b));
}
__device__ __forceinline__ float2 unpack2(u64 v) {
    float2 r; asm("mov.b64 {%0, %1}, %2;" : "=f"(r.x), "=f"(r.y) : "l"(v)); return r;
}

// ---------------------------------------------------------------------------
// Kernel A: x = gelu(LN(concat(vis,lang,state) @ Wf + bf))
// Block tile: 64 rows x 256 cols. Column-pair layout: lane owns cols 2*tx+64*j.
// ---------------------------------------------------------------------------
__global__ __launch_bounds__(256) void fusion_kernel(
    const float* __restrict__ vis, const float* __restrict__ lang,
    const float* __restrict__ state, const float* __restrict__ Wf,
    const float* __restrict__ bf, const float* __restrict__ gf,
    const float* __restrict__ bfln)
{
    __shared__ float As[64][16];
    __shared__ float Bs[16][256];

    const int tid = threadIdx.x;
    const int tx = tid & 31;       // lane -> column-pair group
    const int ty = tid >> 5;       // warp -> 8-row group
    const int row0 = blockIdx.x * 64;

    u64 acc[8][4];
#pragma unroll
    for (int i = 0; i < 8; i++)
#pragma unroll
        for (int j = 0; j < 4; j++) acc[i][j] = 0ull;

    for (int kk = 0; kk < D_IN; kk += 16) {
        // A tile: 64x16 floats = 256 float4, one per thread
        {
            int r = tid >> 2;
            int c4 = (tid & 3) << 2;
            int gk = kk + c4;
            const float* srcp; int stride; int col;
            if (gk < D_VIS)               { srcp = vis;   stride = D_VIS;   col = gk; }
            else if (gk < D_VIS + D_LANG) { srcp = lang;  stride = D_LANG;  col = gk - D_VIS; }
            else                          { srcp = state; stride = D_STATE; col = gk - D_VIS - D_LANG; }
            float4 v = *(const float4*)(srcp + (size_t)(row0 + r) * stride + col);
            As[r][c4 + 0] = v.x; As[r][c4 + 1] = v.y;
            As[r][c4 + 2] = v.z; As[r][c4 + 3] = v.w;
        }
        // B tile: 16x256 floats = 1024 float4, 4 per thread (coalesced)
#pragma unroll
        for (int i = 0; i < 4; i++) {
            int idx = tid + i * 256;          // float4 index
            int r = idx >> 6;                 // 64 float4 per row
            int c = (idx & 63) << 2;
            *(float4*)&Bs[r][c] = *(const float4*)(Wf + (size_t)(kk + r) * D_MODEL + c);
        }
        __syncthreads();
#pragma unroll
        for (int k = 0; k < 16; k++) {
            u64 bp[4];
#pragma unroll
            for (int j = 0; j < 4; j++)
                bp[j] = *(const u64*)&Bs[k][2 * tx + 64 * j];
#pragma unroll
            for (int i = 0; i < 8; i++) {
                float av = As[ty * 8 + i][k];
                u64 ap = pack2(av, av);
#pragma unroll
                for (int j = 0; j < 4; j++) fma2(acc[i][j], ap, bp[j]);
            }
        }
        __syncthreads();
    }

    // Epilogue: +bias, LayerNorm per row (warp holds full row), GELU, store
    float2 bfv[4], gv[4], bv[4];
#pragma unroll
    for (int j = 0; j < 4; j++) {
        int n = 2 * tx + 64 * j;
        bfv[j] = *(const float2*)(bf + n);
        gv[j]  = *(const float2*)(gf + n);
        bv[j]  = *(const float2*)(bfln + n);
    }
#pragma unroll
    for (int i = 0; i < 8; i++) {
        int row = row0 + ty * 8 + i;
        float v[8];
        float s = 0.f;
#pragma unroll
        for (int j = 0; j < 4; j++) {
            float2 p = unpack2(acc[i][j]);
            v[2 * j]     = p.x + bfv[j].x;
            v[2 * j + 1] = p.y + bfv[j].y;
            s += v[2 * j] + v[2 * j + 1];
        }
#pragma unroll
        for (int off = 16; off; off >>= 1) s += __shfl_xor_sync(0xffffffffu, s, off);
        float mu = s * (1.f / 256.f);
        float vs = 0.f;
#pragma unroll
        for (int j = 0; j < 8; j++) { float d = v[j] - mu; vs += d * d; }
#pragma unroll
        for (int off = 16; off; off >>= 1) vs += __shfl_xor_sync(0xffffffffu, vs, off);
        float rstd = rsqrtf(vs * (1.f / 256.f) + 1e-5f);
#pragma unroll
        for (int j = 0; j < 4; j++) {
            float y0 = gv[j].x * (v[2 * j]     - mu) * rstd + bv[j].x;
            float y1 = gv[j].y * (v[2 * j + 1] - mu) * rstd + bv[j].y;
            *(float2*)&g_x[(size_t)row * D_MODEL + 2 * tx + 64 * j] =
                make_float2(gelu_exact(y0), gelu_exact(y1));
        }
    }
}

// ---------------------------------------------------------------------------
// Kernel B: gate — logits, softmax, top-2, top-2 softmax weights,
// deterministic per-block partial sums for load-balance loss.
// One warp per token, 8 tokens per block, 2048 blocks.
// ---------------------------------------------------------------------------
__global__ __launch_bounds__(256) void gate_kernel(const float* __restrict__ Wg)
{
    const int tid = threadIdx.x, lane = tid & 31, w = tid >> 5;
    const int t = blockIdx.x * 8 + w;

    float p0 = 0.f, p1 = 0.f, p2 = 0.f, p3 = 0.f;
    const float* xr = g_x + (size_t)t * D_MODEL;
#pragma unroll
    for (int j = 0; j < 8; j++) {
        int c = lane + 32 * j;
        float xv = xr[c];
        float4 wg = *(const float4*)(Wg + c * 4);
        p0 = fmaf(xv, wg.x, p0); p1 = fmaf(xv, wg.y, p1);
        p2 = fmaf(xv, wg.z, p2); p3 = fmaf(xv, wg.w, p3);
    }
#pragma unroll
    for (int off = 16; off; off >>= 1) {
        p0 += __shfl_xor_sync(0xffffffffu, p0, off);
        p1 += __shfl_xor_sync(0xffffffffu, p1, off);
        p2 += __shfl_xor_sync(0xffffffffu, p2, off);
        p3 += __shfl_xor_sync(0xffffffffu, p3, off);
    }

    __shared__ float sprob[8][4];
    __shared__ float scnt[8][4];
    if (lane == 0) {
        float l[4] = {p0, p1, p2, p3};
        float mx = fmaxf(fmaxf(l[0], l[1]), fmaxf(l[2], l[3]));
        float e[4], se = 0.f;
#pragma unroll
        for (int i = 0; i < 4; i++) { e[i] = expf(l[i] - mx); se += e[i]; }
        float inv = 1.f / se;
#pragma unroll
        for (int i = 0; i < 4; i++) sprob[w][i] = e[i] * inv;

        // top-2 (ties -> lower index, matching jax top_k)
        int i0 = 0;
#pragma unroll
        for (int i = 1; i < 4; i++) if (l[i] > l[i0]) i0 = i;
        int i1 = -1;
#pragma unroll
        for (int i = 0; i < 4; i++) {
            if (i == i0) continue;
            if (i1 < 0 || l[i] > l[i1]) i1 = i;
        }
        float w0 = 1.f / (1.f + expf(l[i1] - l[i0]));
        g_topidx[t] = i0 | (i1 << 8);
        g_topw[2 * t]     = w0;
        g_topw[2 * t + 1] = 1.f - w0;
#pragma unroll
        for (int i = 0; i < 4; i++) scnt[w][i] = (i == i0 || i == i1) ? 1.f : 0.f;
    }
    __syncthreads();
    // fixed-order (deterministic) per-block reduction
    if (tid < 4) {
        float s = 0.f;
        for (int ww = 0; ww < 8; ww++) s += sprob[ww][tid];
        g_partial[blockIdx.x * 8 + tid] = s;
    } else if (tid < 8) {
        int e = tid - 4;
        float s = 0.f;
        for (int ww = 0; ww < 8; ww++) s += scnt[ww][e];
        g_partial[blockIdx.x * 8 + tid] = s;
    }
}

// ---------------------------------------------------------------------------
// Kernel C: fused expert chain per 32-token block.
// x/h1/h2 in SMEM, weights streamed via SMEM staging tile (L2-resident).
// Dynamic SMEM: 40960 floats = 160 KB. Column-pair (f32x2) math throughout.
// ---------------------------------------------------------------------------
extern __shared__ float smemC[];

__global__ __launch_bounds__(256, 1) void expert_kernel(
    const float* __restrict__ W1, const float* __restrict__ b1,
    const float* __restrict__ W2, const float* __restrict__ b2,
    const float* __restrict__ W3, const float* __restrict__ b3,
    const float* __restrict__ eg, const float* __restrict__ eb,
    float* __restrict__ out)
{
    float* x_s  = smemC;            // [32][256]
    float* h1_s = smemC + 8192;     // [32][512]
    float* h2_s = smemC + 24576;    // [32][256]
    float* w_s  = smemC + 32768;    // 8192-float staging

    const int tid = threadIdx.x, tx = tid & 31, ty = tid >> 5;
    const int t0 = blockIdx.x * 32;
    const int rowbase = ty * 4;

    // load x tile (2048 float4, 8 per thread)
#pragma unroll
    for (int i = 0; i < 8; i++) {
        int idx = tid + i * 256;
        int r = idx >> 6;
        int c = (idx & 63) << 2;
        *(float4*)&x_s[r * 256 + c] = *(const float4*)(g_x + (size_t)(t0 + r) * 256 + c);
    }
    // routing info for my 4 rows (uniform across lanes of warp)
    int idxp[4]; float w0_[4], w1_[4];
#pragma unroll
    for (int jm = 0; jm < 4; jm++) {
        int t = t0 + rowbase + jm;
        idxp[jm] = g_topidx[t];
        w0_[jm] = g_topw[2 * t];
        w1_[jm] = g_topw[2 * t + 1];
    }
    float out_acc[4][8];
#pragma unroll
    for (int jm = 0; jm < 4; jm++)
#pragma unroll
        for (int jn = 0; jn < 8; jn++) out_acc[jm][jn] = 0.f;
    __syncthreads();

    for (int e = 0; e < N_EXP; e++) {
        // ---------- GEMM1: h1 = gelu(x @ W1[e] + b1[e])  [32x512], K=256
        const float* W1e = W1 + (size_t)e * 256 * 512;
        {
            u64 acc1[4][8];
#pragma unroll
            for (int jm = 0; jm < 4; jm++)
#pragma unroll
                for (int p = 0; p < 8; p++) acc1[jm][p] = 0ull;

            for (int kk = 0; kk < 256; kk += 16) {
#pragma unroll
                for (int i = 0; i < 8; i++) {
                    int idx = tid + i * 256;        // 2048 float4 total
                    int r = idx >> 7;               // 128 float4 per 512-row
                    int c = (idx & 127) << 2;
                    *(float4*)&w_s[r * 512 + c] =
                        *(const float4*)(W1e + (size_t)(kk + r) * 512 + c);
                }
                __syncthreads();
#pragma unroll
                for (int k = 0; k < 16; k++) {
                    u64 wp[8];
#pragma unroll
                    for (int p = 0; p < 8; p++)
                        wp[p] = *(const u64*)&w_s[k * 512 + 2 * tx + 64 * p];
#pragma unroll
                    for (int jm = 0; jm < 4; jm++) {
                        float av = x_s[(rowbase + jm) * 256 + kk + k];
                        u64 ap = pack2(av, av);
#pragma unroll
                        for (int p = 0; p < 8; p++) fma2(acc1[jm][p], ap, wp[p]);
                    }
                }
                __syncthreads();
            }
#pragma unroll
            for (int p = 0; p < 8; p++) {
                int n = 2 * tx + 64 * p;
                float2 bb = *(const float2*)(b1 + e * 512 + n);
#pragma unroll
                for (int jm = 0; jm < 4; jm++) {
                    float2 v = unpack2(acc1[jm][p]);
                    *(float2*)&h1_s[(rowbase + jm) * 512 + n] =
                        make_float2(gelu_exact(v.x + bb.x), gelu_exact(v.y + bb.y));
                }
            }
            __syncthreads();
        }

        // ---------- GEMM2: h2 = gelu(h1 @ W2[e] + b2[e])  [32x256], K=512
        const float* W2e = W2 + (size_t)e * 512 * 256;
        {
            u64 acc2[4][4];
#pragma unroll
            for (int jm = 0; jm < 4; jm++)
#pragma unroll
                for (int p = 0; p < 4; p++) acc2[jm][p] = 0ull;

            for (int kk = 0; kk < 512; kk += 32) {
#pragma unroll
                for (int i = 0; i < 8; i++) {
                    int idx = tid + i * 256;
                    int r = idx >> 6;
                    int c = (idx & 63) << 2;
                    *(float4*)&w_s[r * 256 + c] =
                        *(const float4*)(W2e + (size_t)(kk + r) * 256 + c);
                }
                __syncthreads();
#pragma unroll
                for (int k = 0; k < 32; k++) {
                    u64 wp[4];
#pragma unroll
                    for (int p = 0; p < 4; p++)
                        wp[p] = *(const u64*)&w_s[k * 256 + 2 * tx + 64 * p];
#pragma unroll
                    for (int jm = 0; jm < 4; jm++) {
                        float av = h1_s[(rowbase + jm) * 512 + kk + k];
                        u64 ap = pack2(av, av);
#pragma unroll
                        for (int p = 0; p < 4; p++) fma2(acc2[jm][p], ap, wp[p]);
                    }
                }
                __syncthreads();
            }
#pragma unroll
            for (int p = 0; p < 4; p++) {
                int n = 2 * tx + 64 * p;
                float2 bb = *(const float2*)(b2 + e * 256 + n);
#pragma unroll
                for (int jm = 0; jm < 4; jm++) {
                    float2 v = unpack2(acc2[jm][p]);
                    *(float2*)&h2_s[(rowbase + jm) * 256 + n] =
                        make_float2(gelu_exact(v.x + bb.x), gelu_exact(v.y + bb.y));
                }
            }
            __syncthreads();
        }

        // ---------- GEMM3: h3 = h2 @ W3[e] + b3[e]  [32x256], K=256 (regs)
        const float* W3e = W3 + (size_t)e * 256 * 256;
        u64 acc3[4][4];
#pragma unroll
        for (int jm = 0; jm < 4; jm++)
#pragma unroll
            for (int p = 0; p < 4; p++) acc3[jm][p] = 0ull;

        for (int kk = 0; kk < 256; kk += 32) {
#pragma unroll
            for (int i = 0; i < 8; i++) {
                int idx = tid + i * 256;
                int r = idx >> 6;
                int c = (idx & 63) << 2;
                *(float4*)&w_s[r * 256 + c] =
                    *(const float4*)(W3e + (size_t)(kk + r) * 256 + c);
            }
            __syncthreads();
#pragma unroll
            for (int k = 0; k < 32; k++) {
                u64 wp[4];
#pragma unroll
                for (int p = 0; p < 4; p++)
                    wp[p] = *(const u64*)&w_s[k * 256 + 2 * tx + 64 * p];
#pragma unroll
                for (int jm = 0; jm < 4; jm++) {
                    float av = h2_s[(rowbase + jm) * 256 + kk + k];
                    u64 ap = pack2(av, av);
#pragma unroll
                    for (int p = 0; p < 4; p++) fma2(acc3[jm][p], ap, wp[p]);
                }
            }
            __syncthreads();
        }

        // ---------- Epilogue: LN(x + h3) with eg/eb, combine with top-k weight
        float2 b3v[4], egv[4], ebv[4];
#pragma unroll
        for (int p = 0; p < 4; p++) {
            int n = 2 * tx + 64 * p;
            b3v[p] = *(const float2*)(b3 + e * 256 + n);
            egv[p] = *(const float2*)(eg + e * 256 + n);
            ebv[p] = *(const float2*)(eb + e * 256 + n);
        }
#pragma unroll
        for (int jm = 0; jm < 4; jm++) {
            int i0 = idxp[jm] & 0xff, i1 = idxp[jm] >> 8;
            float wsel = (e == i0) ? w0_[jm] : ((e == i1) ? w1_[jm] : 0.f);
            if (wsel != 0.f) {              // uniform across the warp
                float vrow[8];
                float s = 0.f;
#pragma unroll
                for (int p = 0; p < 4; p++) {
                    float2 h = unpack2(acc3[jm][p]);
                    float2 xv = *(const float2*)&x_s[(rowbase + jm) * 256 + 2 * tx + 64 * p];
                    vrow[2 * p]     = h.x + b3v[p].x + xv.x;
                    vrow[2 * p + 1] = h.y + b3v[p].y + xv.y;
                    s += vrow[2 * p] + vrow[2 * p + 1];
                }
#pragma unroll
                for (int off = 16; off; off >>= 1) s += __shfl_xor_sync(0xffffffffu, s, off);
                float mu = s * (1.f / 256.f);
                float vs = 0.f;
#pragma unroll
                for (int jn = 0; jn < 8; jn++) { float d = vrow[jn] - mu; vs += d * d; }
#pragma unroll
                for (int off = 16; off; off >>= 1) vs += __shfl_xor_sync(0xffffffffu, vs, off);
                float rstd = rsqrtf(vs * (1.f / 256.f) + 1e-5f);
#pragma unroll
                for (int p = 0; p < 4; p++) {
                    float y0 = egv[p].x * (vrow[2 * p]     - mu) * rstd + ebv[p].x;
                    float y1 = egv[p].y * (vrow[2 * p + 1] - mu) * rstd + ebv[p].y;
                    out_acc[jm][2 * p]     = fmaf(wsel, y0, out_acc[jm][2 * p]);
                    out_acc[jm][2 * p + 1] = fmaf(wsel, y1, out_acc[jm][2 * p + 1]);
                }
            }
        }
        // next expert restages w_s after its own __syncthreads(); safe because
        // this epilogue touches only x_s/registers.
    }

    // write out (coalesced float2 per lane)
#pragma unroll
    for (int jm = 0; jm < 4; jm++)
#pragma unroll
        for (int p = 0; p < 4; p++)
            *(float2*)&out[(size_t)(t0 + rowbase + jm) * 256 + 2 * tx + 64 * p] =
                make_float2(out_acc[jm][2 * p], out_acc[jm][2 * p + 1]);
}

// ---------------------------------------------------------------------------
// Kernel D: deterministic final reduction for load-balance loss
// ---------------------------------------------------------------------------
__global__ __launch_bounds__(256) void loss_kernel(float* __restrict__ out, int out_size)
{
    __shared__ float sh[256];
    __shared__ float totals[8];
    int tid = threadIdx.x;
    float acc[8];
#pragma unroll
    for (int f = 0; f < 8; f++) acc[f] = 0.f;
    for (int i = tid; i < 2048; i += 256) {
#pragma unroll
        for (int f = 0; f < 8; f++) acc[f] += g_partial[i * 8 + f];
    }
    for (int f = 0; f < 8; f++) {
        sh[tid] = acc[f];
        __syncthreads();
        for (int s = 128; s > 0; s >>= 1) {
            if (tid < s) sh[tid] += sh[tid + s];
            __syncthreads();
        }
        if (tid == 0) totals[f] = sh[0];
        __syncthreads();
    }
    if (tid == 0 && out_size > B_TOK * D_MODEL) {
        float loss = 0.f;
#pragma unroll
        for (int i = 0; i < 4; i++) {
            float f_i = totals[4 + i] / (float)(B_TOK * TOPK);
            float pm  = totals[i] / (float)B_TOK;
            loss += f_i * pm;
        }
        out[B_TOK * D_MODEL] = (float)N_EXP * loss;
    }
}

// ---------------------------------------------------------------------------
extern "C" void kernel_launch(void* const* d_in, const int* in_sizes, int n_in,
                              void* d_out, int out_size)
{
    const float* vis   = (const float*)d_in[0];
    const float* lang  = (const float*)d_in[1];
    const float* state = (const float*)d_in[2];
    const float* Wf    = (const float*)d_in[3];
    const float* bf    = (const float*)d_in[4];
    const float* gf    = (const float*)d_in[5];
    const float* bfln  = (const float*)d_in[6];
    const float* Wg    = (const float*)d_in[7];
    const float* W1    = (const float*)d_in[8];
    const float* b1    = (const float*)d_in[9];
    const float* W2    = (const float*)d_in[10];
    const float* b2    = (const float*)d_in[11];
    const float* W3    = (const float*)d_in[12];
    const float* b3    = (const float*)d_in[13];
    const float* eg    = (const float*)d_in[14];
    const float* eb    = (const float*)d_in[15];
    float* out = (float*)d_out;

    cudaFuncSetAttribute(expert_kernel,
                         cudaFuncAttributeMaxDynamicSharedMemorySize, 163840);

    fusion_kernel<<<B_TOK / 64, 256>>>(vis, lang, state, Wf, bf, gf, bfln);
    gate_kernel<<<B_TOK / 8, 256>>>(Wg);
    expert_kernel<<<B_TOK / 32, 256, 163840>>>(W1, b1, W2, b2, W3, b3, eg, eb, out);
    loss_kernel<<<1, 256>>>(out, out_size);
}

// round 5
// speedup vs baseline: 1.7681x; 1.7681x over previous
#include <cuda_runtime.h>
#include <cuda_bf16.h>
#include <math.h>

// Problem constants
#define B_TOK   16384
#define D_VIS   768
#define D_LANG  768
#define D_STATE 64
#define D_IN    1600
#define D_MODEL 256
#define N_EXP   4
#define TOPK    2
#define MAXB    518           // max expert blocks after per-bucket padding
#define PERM_N  (MAXB * 32)   // 16576

typedef unsigned long long u64;

// ---------------------------------------------------------------------------
// Scratch
// ---------------------------------------------------------------------------
__device__ float g_x[B_TOK * D_MODEL];
__device__ int   g_topidx[B_TOK];             // i0 | (i1<<8)
__device__ float g_topw[B_TOK * 2];
__device__ float g_partial[2048 * 8];
__device__ int   g_bcount[8];                 // per-pair-bucket counts
__device__ int   g_off[8];                    // padded bucket offsets [0..6]
__device__ int   g_pair_slot[B_TOK];          // pid | (slot<<4)
__device__ int   g_perm[PERM_N];              // token index or -1

__device__ __forceinline__ float gelu_exact(float v) {
    return 0.5f * v * (1.f + erff(v * 0.70710678118654752f));
}

// ---- packed fp32 helpers ---------------------------------------------------
__device__ __forceinline__ u64 pack2(float x, float y) {
    u64 r; asm("mov.b64 %0, {%1, %2};" : "=l"(r) : "f"(x), "f"(y)); return r;
}
__device__ __forceinline__ void fma2(u64& d, u64 a, u64 b) {
    asm("fma.rn.f32x2 %0, %1, %2, %0;" : "+l"(d) : "l"(a), "l"(b));
}
__device__ __forceinline__ float2 unpack2(u64 v) {
    float2 r; asm("mov.b64 {%0, %1}, %2;" : "=f"(r.x), "=f"(r.y) : "l"(v)); return r;
}

// ---- cp.async helpers ------------------------------------------------------
__device__ __forceinline__ void cp16(unsigned saddr, const void* g) {
    asm volatile("cp.async.cg.shared.global [%0], [%1], 16;" :: "r"(saddr), "l"(g));
}
__device__ __forceinline__ void cp_commit() { asm volatile("cp.async.commit_group;"); }
__device__ __forceinline__ void cp_wait1()  { asm volatile("cp.async.wait_group 1;"); }
__device__ __forceinline__ void cp_wait0()  { asm volatile("cp.async.wait_group 0;"); }

// stage = 8192 floats (32KB), 2048 float4, 8 per thread
__device__ __forceinline__ void stage_issue(unsigned sbuf, const float* gsrc, int tid) {
#pragma unroll
    for (int i = 0; i < 8; i++) {
        int idx = tid + i * 256;
        cp16(sbuf + idx * 16, (const void*)(gsrc + idx * 4));
    }
    cp_commit();
}

// ---------------------------------------------------------------------------
// Kernel A: x = gelu(LN(concat @ Wf + bf))   (64x256 tile per block)
// ---------------------------------------------------------------------------
__global__ __launch_bounds__(256) void fusion_kernel(
    const float* __restrict__ vis, const float* __restrict__ lang,
    const float* __restrict__ state, const float* __restrict__ Wf,
    const float* __restrict__ bf, const float* __restrict__ gf,
    const float* __restrict__ bfln)
{
    __shared__ float As[64][16];
    __shared__ float Bs[16][256];

    const int tid = threadIdx.x;
    const int tx = tid & 31;
    const int ty = tid >> 5;
    const int row0 = blockIdx.x * 64;

    if (blockIdx.x == 0 && tid < 8) g_bcount[tid] = 0;   // reset for gate atomics

    u64 acc[8][4];
#pragma unroll
    for (int i = 0; i < 8; i++)
#pragma unroll
        for (int j = 0; j < 4; j++) acc[i][j] = 0ull;

    for (int kk = 0; kk < D_IN; kk += 16) {
        {
            int r = tid >> 2;
            int c4 = (tid & 3) << 2;
            int gk = kk + c4;
            const float* srcp; int stride; int col;
            if (gk < D_VIS)               { srcp = vis;   stride = D_VIS;   col = gk; }
            else if (gk < D_VIS + D_LANG) { srcp = lang;  stride = D_LANG;  col = gk - D_VIS; }
            else                          { srcp = state; stride = D_STATE; col = gk - D_VIS - D_LANG; }
            float4 v = *(const float4*)(srcp + (size_t)(row0 + r) * stride + col);
            As[r][c4 + 0] = v.x; As[r][c4 + 1] = v.y;
            As[r][c4 + 2] = v.z; As[r][c4 + 3] = v.w;
        }
#pragma unroll
        for (int i = 0; i < 4; i++) {
            int idx = tid + i * 256;
            int r = idx >> 6;
            int c = (idx & 63) << 2;
            *(float4*)&Bs[r][c] = *(const float4*)(Wf + (size_t)(kk + r) * D_MODEL + c);
        }
        __syncthreads();
#pragma unroll 4
        for (int k = 0; k < 16; k++) {
            u64 bp[4];
#pragma unroll
            for (int j = 0; j < 4; j++)
                bp[j] = *(const u64*)&Bs[k][2 * tx + 64 * j];
#pragma unroll
            for (int i = 0; i < 8; i++) {
                float av = As[ty * 8 + i][k];
                u64 ap = pack2(av, av);
#pragma unroll
                for (int j = 0; j < 4; j++) fma2(acc[i][j], ap, bp[j]);
            }
        }
        __syncthreads();
    }

    float2 bfv[4], gv[4], bv[4];
#pragma unroll
    for (int j = 0; j < 4; j++) {
        int n = 2 * tx + 64 * j;
        bfv[j] = *(const float2*)(bf + n);
        gv[j]  = *(const float2*)(gf + n);
        bv[j]  = *(const float2*)(bfln + n);
    }
#pragma unroll
    for (int i = 0; i < 8; i++) {
        int row = row0 + ty * 8 + i;
        float v[8];
        float s = 0.f;
#pragma unroll
        for (int j = 0; j < 4; j++) {
            float2 p = unpack2(acc[i][j]);
            v[2 * j]     = p.x + bfv[j].x;
            v[2 * j + 1] = p.y + bfv[j].y;
            s += v[2 * j] + v[2 * j + 1];
        }
#pragma unroll
        for (int off = 16; off; off >>= 1) s += __shfl_xor_sync(0xffffffffu, s, off);
        float mu = s * (1.f / 256.f);
        float vs = 0.f;
#pragma unroll
        for (int j = 0; j < 8; j++) { float d = v[j] - mu; vs += d * d; }
#pragma unroll
        for (int off = 16; off; off >>= 1) vs += __shfl_xor_sync(0xffffffffu, vs, off);
        float rstd = rsqrtf(vs * (1.f / 256.f) + 1e-5f);
#pragma unroll
        for (int j = 0; j < 4; j++) {
            float y0 = gv[j].x * (v[2 * j]     - mu) * rstd + bv[j].x;
            float y1 = gv[j].y * (v[2 * j + 1] - mu) * rstd + bv[j].y;
            *(float2*)&g_x[(size_t)row * D_MODEL + 2 * tx + 64 * j] =
                make_float2(gelu_exact(y0), gelu_exact(y1));
        }
    }
}

// ---------------------------------------------------------------------------
// Kernel B: gate + top-2 + pair-bucket slot assignment + lb-loss partials
// ---------------------------------------------------------------------------
__global__ __launch_bounds__(256) void gate_kernel(const float* __restrict__ Wg)
{
    const int tid = threadIdx.x, lane = tid & 31, w = tid >> 5;
    const int t = blockIdx.x * 8 + w;

    float p0 = 0.f, p1 = 0.f, p2 = 0.f, p3 = 0.f;
    const float* xr = g_x + (size_t)t * D_MODEL;
#pragma unroll
    for (int j = 0; j < 8; j++) {
        int c = lane + 32 * j;
        float xv = xr[c];
        float4 wg = *(const float4*)(Wg + c * 4);
        p0 = fmaf(xv, wg.x, p0); p1 = fmaf(xv, wg.y, p1);
        p2 = fmaf(xv, wg.z, p2); p3 = fmaf(xv, wg.w, p3);
    }
#pragma unroll
    for (int off = 16; off; off >>= 1) {
        p0 += __shfl_xor_sync(0xffffffffu, p0, off);
        p1 += __shfl_xor_sync(0xffffffffu, p1, off);
        p2 += __shfl_xor_sync(0xffffffffu, p2, off);
        p3 += __shfl_xor_sync(0xffffffffu, p3, off);
    }

    __shared__ float sprob[8][4];
    __shared__ float scnt[8][4];
    if (lane == 0) {
        float l[4] = {p0, p1, p2, p3};
        float mx = fmaxf(fmaxf(l[0], l[1]), fmaxf(l[2], l[3]));
        float e[4], se = 0.f;
#pragma unroll
        for (int i = 0; i < 4; i++) { e[i] = expf(l[i] - mx); se += e[i]; }
        float inv = 1.f / se;
#pragma unroll
        for (int i = 0; i < 4; i++) sprob[w][i] = e[i] * inv;

        int i0 = 0;
#pragma unroll
        for (int i = 1; i < 4; i++) if (l[i] > l[i0]) i0 = i;
        int i1 = -1;
#pragma unroll
        for (int i = 0; i < 4; i++) {
            if (i == i0) continue;
            if (i1 < 0 || l[i] > l[i1]) i1 = i;
        }
        float w0 = 1.f / (1.f + expf(l[i1] - l[i0]));
        g_topidx[t] = i0 | (i1 << 8);
        g_topw[2 * t]     = w0;
        g_topw[2 * t + 1] = 1.f - w0;
#pragma unroll
        for (int i = 0; i < 4; i++) scnt[w][i] = (i == i0 || i == i1) ? 1.f : 0.f;

        // unordered pair bucket (triangular index, E=4):
        // (0,1)=0 (0,2)=1 (0,3)=2 (1,2)=3 (1,3)=4 (2,3)=5
        int a = min(i0, i1), b = max(i0, i1);
        int pid = (a * (7 - a)) / 2 + (b - a - 1);
        int slot = atomicAdd(&g_bcount[pid], 1);
        g_pair_slot[t] = pid | (slot << 4);
    }
    __syncthreads();
    if (tid < 4) {
        float s = 0.f;
        for (int ww = 0; ww < 8; ww++) s += sprob[ww][tid];
        g_partial[blockIdx.x * 8 + tid] = s;
    } else if (tid < 8) {
        int e = tid - 4;
        float s = 0.f;
        for (int ww = 0; ww < 8; ww++) s += scnt[ww][e];
        g_partial[blockIdx.x * 8 + tid] = s;
    }
}

// ---------------------------------------------------------------------------
// Kernel B2: padded bucket offsets + perm init
// ---------------------------------------------------------------------------
__global__ __launch_bounds__(256) void offsets_kernel()
{
    int tid = threadIdx.x;
    for (int i = tid; i < PERM_N; i += 256) g_perm[i] = -1;
    if (tid == 0) {
        int o = 0;
#pragma unroll
        for (int p = 0; p < 6; p++) {
            g_off[p] = o;
            o += (g_bcount[p] + 31) & ~31;
        }
        g_off[6] = o;
    }
}

// ---------------------------------------------------------------------------
// Kernel B3: scatter tokens into bucketed permutation
// ---------------------------------------------------------------------------
__global__ __launch_bounds__(256) void scatter_kernel()
{
    int t = blockIdx.x * 256 + threadIdx.x;
    if (t < B_TOK) {
        int ps = g_pair_slot[t];
        int pid = ps & 15, slot = ps >> 4;
        g_perm[g_off[pid] + slot] = t;
    }
}

// ---------------------------------------------------------------------------
// Kernel C: bucketed expert chain — 32 tokens/block, only the 2 selected
// experts. 8-row x {4,2}-pair register tiles; cp.async double-buffered
// weight staging (2x32KB). Dynamic SMEM = 192KB.
// ---------------------------------------------------------------------------
extern __shared__ float smemC[];

__global__ __launch_bounds__(256, 1) void expert_kernel(
    const float* __restrict__ W1, const float* __restrict__ b1,
    const float* __restrict__ W2, const float* __restrict__ b2,
    const float* __restrict__ W3, const float* __restrict__ b3,
    const float* __restrict__ eg, const float* __restrict__ eb,
    float* __restrict__ out)
{
    float* x_s  = smemC;            // [32][256]  32KB
    float* h1_s = smemC + 8192;     // [32][512]  64KB
    float* h2_s = smemC + 24576;    // [32][256]  32KB
    float* w_s  = smemC + 32768;    // 2 x 8192   64KB
    __shared__ int   s_tok[32];
    __shared__ float ln_s[32][4];

    const int tid = threadIdx.x, tx = tid & 31, wid = tid >> 5;
    const int rowgrp = wid >> 1, colgrp = wid & 1;
    const int rowbase = rowgrp * 8;
    const int base = blockIdx.x * 32;

    int off6 = g_off[6];
    if (base >= off6) return;
    int pid = 0;
#pragma unroll
    for (int p = 0; p < 5; p++) if (base >= g_off[p + 1]) pid = p + 1;
    const int pe0[6] = {0, 0, 0, 1, 1, 2};
    const int pe1[6] = {1, 2, 3, 2, 3, 3};
    const int e0 = pe0[pid], e1 = pe1[pid];

    if (tid < 32) s_tok[tid] = g_perm[base + tid];
    __syncthreads();

    // gather x tile
#pragma unroll
    for (int i = 0; i < 8; i++) {
        int idx = tid + i * 256;
        int r = idx >> 6, c = (idx & 63) << 2;
        int tk = s_tok[r]; if (tk < 0) tk = 0;
        *(float4*)&x_s[r * 256 + c] = *(const float4*)(g_x + (size_t)tk * 256 + c);
    }

    float out_acc[8][4];
#pragma unroll
    for (int jm = 0; jm < 8; jm++)
#pragma unroll
        for (int j = 0; j < 4; j++) out_acc[jm][j] = 0.f;
    __syncthreads();

    const unsigned wu = (unsigned)__cvta_generic_to_shared(w_s);
    const int cb1 = colgrp * 256;   // GEMM1 column base (N=512)
    const int cb2 = colgrp * 128;   // GEMM2/3 column base (N=256)

#pragma unroll 1
    for (int ei = 0; ei < 2; ei++) {
        const int e = ei ? e1 : e0;

        // ================= GEMM1: h1 = gelu(x @ W1[e] + b1)  K=256, N=512
        {
            const float* W1e = W1 + (size_t)e * 256 * 512;
            u64 acc1[8][4];
#pragma unroll
            for (int jm = 0; jm < 8; jm++)
#pragma unroll
                for (int p = 0; p < 4; p++) acc1[jm][p] = 0ull;

            stage_issue(wu, W1e, tid);                       // stage0 -> buf0
#pragma unroll 1
            for (int s = 0; s < 16; s++) {
                if (s + 1 < 16) {
                    stage_issue(wu + ((s + 1) & 1) * 32768, W1e + (size_t)(s + 1) * 16 * 512, tid);
                    cp_wait1();
                } else cp_wait0();
                __syncthreads();
                const float* wb = w_s + (s & 1) * 8192;
                const int kk = s * 16;
#pragma unroll 4
                for (int k2 = 0; k2 < 8; k2++) {
                    u64 a2[8];
#pragma unroll
                    for (int jm = 0; jm < 8; jm++)
                        a2[jm] = *(const u64*)&x_s[(rowbase + jm) * 256 + kk + 2 * k2];
                    u64 wA[4], wB[4];
#pragma unroll
                    for (int p = 0; p < 4; p++) {
                        wA[p] = *(const u64*)&wb[(2 * k2)     * 512 + cb1 + 2 * tx + 64 * p];
                        wB[p] = *(const u64*)&wb[(2 * k2 + 1) * 512 + cb1 + 2 * tx + 64 * p];
                    }
#pragma unroll
                    for (int jm = 0; jm < 8; jm++) {
                        float2 a = unpack2(a2[jm]);
                        u64 ap0 = pack2(a.x, a.x), ap1 = pack2(a.y, a.y);
#pragma unroll
                        for (int p = 0; p < 4; p++) {
                            fma2(acc1[jm][p], ap0, wA[p]);
                            fma2(acc1[jm][p], ap1, wB[p]);
                        }
                    }
                }
                __syncthreads();
            }
#pragma unroll
            for (int p = 0; p < 4; p++) {
                int n = cb1 + 2 * tx + 64 * p;
                float2 bb = *(const float2*)(b1 + e * 512 + n);
#pragma unroll
                for (int jm = 0; jm < 8; jm++) {
                    float2 v = unpack2(acc1[jm][p]);
                    *(float2*)&h1_s[(rowbase + jm) * 512 + n] =
                        make_float2(gelu_exact(v.x + bb.x), gelu_exact(v.y + bb.y));
                }
            }
        }

        // ================= GEMM2: h2 = gelu(h1 @ W2[e] + b2)  K=512, N=256
        {
            const float* W2e = W2 + (size_t)e * 512 * 256;
            u64 acc2[8][2];
#pragma unroll
            for (int jm = 0; jm < 8; jm++)
#pragma unroll
                for (int p = 0; p < 2; p++) acc2[jm][p] = 0ull;

            stage_issue(wu, W2e, tid);
#pragma unroll 1
            for (int s = 0; s < 16; s++) {
                if (s + 1 < 16) {
                    stage_issue(wu + ((s + 1) & 1) * 32768, W2e + (size_t)(s + 1) * 32 * 256, tid);
                    cp_wait1();
                } else cp_wait0();
                __syncthreads();   // also orders h1_s writes (iter 0)
                const float* wb = w_s + (s & 1) * 8192;
                const int kk = s * 32;
#pragma unroll 4
                for (int k2 = 0; k2 < 16; k2++) {
                    u64 a2[8];
#pragma unroll
                    for (int jm = 0; jm < 8; jm++)
                        a2[jm] = *(const u64*)&h1_s[(rowbase + jm) * 512 + kk + 2 * k2];
                    u64 wA[2], wB[2];
#pragma unroll
                    for (int p = 0; p < 2; p++) {
                        wA[p] = *(const u64*)&wb[(2 * k2)     * 256 + cb2 + 2 * tx + 64 * p];
                        wB[p] = *(const u64*)&wb[(2 * k2 + 1) * 256 + cb2 + 2 * tx + 64 * p];
                    }
#pragma unroll
                    for (int jm = 0; jm < 8; jm++) {
                        float2 a = unpack2(a2[jm]);
                        u64 ap0 = pack2(a.x, a.x), ap1 = pack2(a.y, a.y);
#pragma unroll
                        for (int p = 0; p < 2; p++) {
                            fma2(acc2[jm][p], ap0, wA[p]);
                            fma2(acc2[jm][p], ap1, wB[p]);
                        }
                    }
                }
                __syncthreads();
            }
#pragma unroll
            for (int p = 0; p < 2; p++) {
                int n = cb2 + 2 * tx + 64 * p;
                float2 bb = *(const float2*)(b2 + e * 256 + n);
#pragma unroll
                for (int jm = 0; jm < 8; jm++) {
                    float2 v = unpack2(acc2[jm][p]);
                    *(float2*)&h2_s[(rowbase + jm) * 256 + n] =
                        make_float2(gelu_exact(v.x + bb.x), gelu_exact(v.y + bb.y));
                }
            }
        }

        // ================= GEMM3: h3 = h2 @ W3[e] + b3  K=256, N=256
        u64 acc3[8][2];
#pragma unroll
        for (int jm = 0; jm < 8; jm++)
#pragma unroll
            for (int p = 0; p < 2; p++) acc3[jm][p] = 0ull;
        {
            const float* W3e = W3 + (size_t)e * 256 * 256;
            stage_issue(wu, W3e, tid);
#pragma unroll 1
            for (int s = 0; s < 8; s++) {
                if (s + 1 < 8) {
                    stage_issue(wu + ((s + 1) & 1) * 32768, W3e + (size_t)(s + 1) * 32 * 256, tid);
                    cp_wait1();
                } else cp_wait0();
                __syncthreads();   // also orders h2_s writes (iter 0)
                const float* wb = w_s + (s & 1) * 8192;
                const int kk = s * 32;
#pragma unroll 4
                for (int k2 = 0; k2 < 16; k2++) {
                    u64 a2[8];
#pragma unroll
                    for (int jm = 0; jm < 8; jm++)
                        a2[jm] = *(const u64*)&h2_s[(rowbase + jm) * 256 + kk + 2 * k2];
                    u64 wA[2], wB[2];
#pragma unroll
                    for (int p = 0; p < 2; p++) {
                        wA[p] = *(const u64*)&wb[(2 * k2)     * 256 + cb2 + 2 * tx + 64 * p];
                        wB[p] = *(const u64*)&wb[(2 * k2 + 1) * 256 + cb2 + 2 * tx + 64 * p];
                    }
#pragma unroll
                    for (int jm = 0; jm < 8; jm++) {
                        float2 a = unpack2(a2[jm]);
                        u64 ap0 = pack2(a.x, a.x), ap1 = pack2(a.y, a.y);
#pragma unroll
                        for (int p = 0; p < 2; p++) {
                            fma2(acc3[jm][p], ap0, wA[p]);
                            fma2(acc3[jm][p], ap1, wB[p]);
                        }
                    }
                }
                __syncthreads();
            }
        }

        // ================= Epilogue: LN(x + h3), weighted accumulate
        float2 b3v[2], egv[2], ebv[2];
#pragma unroll
        for (int p = 0; p < 2; p++) {
            int n = cb2 + 2 * tx + 64 * p;
            b3v[p] = *(const float2*)(b3 + e * 256 + n);
            egv[p] = *(const float2*)(eg + e * 256 + n);
            ebv[p] = *(const float2*)(eb + e * 256 + n);
        }
        // pass 1: per-row partial sums (row spans 2 warps -> smem combine)
#pragma unroll
        for (int jm = 0; jm < 8; jm++) {
            int row = rowbase + jm;
            float2 h0 = unpack2(acc3[jm][0]), h1v = unpack2(acc3[jm][1]);
            float2 x0 = *(const float2*)&x_s[row * 256 + cb2 + 2 * tx];
            float2 x1 = *(const float2*)&x_s[row * 256 + cb2 + 2 * tx + 64];
            float v0 = h0.x + b3v[0].x + x0.x;
            float v1 = h0.y + b3v[0].y + x0.y;
            float v2 = h1v.x + b3v[1].x + x1.x;
            float v3 = h1v.y + b3v[1].y + x1.y;
            float s4 = v0 + v1 + v2 + v3;
            float ss = v0 * v0 + v1 * v1 + v2 * v2 + v3 * v3;
#pragma unroll
            for (int o = 16; o; o >>= 1) {
                s4 += __shfl_xor_sync(0xffffffffu, s4, o);
                ss += __shfl_xor_sync(0xffffffffu, ss, o);
            }
            if (tx == 0) { ln_s[row][colgrp * 2] = s4; ln_s[row][colgrp * 2 + 1] = ss; }
        }
        __syncthreads();
        // pass 2: normalize + accumulate
#pragma unroll
        for (int jm = 0; jm < 8; jm++) {
            int row = rowbase + jm;
            int tk = s_tok[row];
            float wsel = 0.f;
            if (tk >= 0) {
                int ip = g_topidx[tk];
                wsel = (e == (ip & 0xff)) ? g_topw[2 * tk] : g_topw[2 * tk + 1];
            }
            float sm = ln_s[row][0] + ln_s[row][2];
            float sq = ln_s[row][1] + ln_s[row][3];
            float mu = sm * (1.f / 256.f);
            float var = sq * (1.f / 256.f) - mu * mu;
            float rstd = rsqrtf(var + 1e-5f);
            float2 h0 = unpack2(acc3[jm][0]), h1v = unpack2(acc3[jm][1]);
            float2 x0 = *(const float2*)&x_s[row * 256 + cb2 + 2 * tx];
            float2 x1 = *(const float2*)&x_s[row * 256 + cb2 + 2 * tx + 64];
            float v[4] = { h0.x + b3v[0].x + x0.x, h0.y + b3v[0].y + x0.y,
                           h1v.x + b3v[1].x + x1.x, h1v.y + b3v[1].y + x1.y };
            float gvv[4] = { egv[0].x, egv[0].y, egv[1].x, egv[1].y };
            float bvv[4] = { ebv[0].x, ebv[0].y, ebv[1].x, ebv[1].y };
#pragma unroll
            for (int j = 0; j < 4; j++) {
                float y = gvv[j] * (v[j] - mu) * rstd + bvv[j];
                out_acc[jm][j] = fmaf(wsel, y, out_acc[jm][j]);
            }
        }
        __syncthreads();
    }

    // store (each valid token written exactly once)
#pragma unroll
    for (int jm = 0; jm < 8; jm++) {
        int row = rowbase + jm;
        int tk = s_tok[row];
        if (tk >= 0) {
            *(float2*)&out[(size_t)tk * 256 + cb2 + 2 * tx] =
                make_float2(out_acc[jm][0], out_acc[jm][1]);
            *(float2*)&out[(size_t)tk * 256 + cb2 + 2 * tx + 64] =
                make_float2(out_acc[jm][2], out_acc[jm][3]);
        }
    }
}

// ---------------------------------------------------------------------------
// Kernel D: deterministic final reduction for load-balance loss
// ---------------------------------------------------------------------------
__global__ __launch_bounds__(256) void loss_kernel(float* __restrict__ out, int out_size)
{
    __shared__ float sh[256];
    __shared__ float totals[8];
    int tid = threadIdx.x;
    float acc[8];
#pragma unroll
    for (int f = 0; f < 8; f++) acc[f] = 0.f;
    for (int i = tid; i < 2048; i += 256) {
#pragma unroll
        for (int f = 0; f < 8; f++) acc[f] += g_partial[i * 8 + f];
    }
    for (int f = 0; f < 8; f++) {
        sh[tid] = acc[f];
        __syncthreads();
        for (int s = 128; s > 0; s >>= 1) {
            if (tid < s) sh[tid] += sh[tid + s];
            __syncthreads();
        }
        if (tid == 0) totals[f] = sh[0];
        __syncthreads();
    }
    if (tid == 0 && out_size > B_TOK * D_MODEL) {
        float loss = 0.f;
#pragma unroll
        for (int i = 0; i < 4; i++) {
            float f_i = totals[4 + i] / (float)(B_TOK * TOPK);
            float pm  = totals[i] / (float)B_TOK;
            loss += f_i * pm;
        }
        out[B_TOK * D_MODEL] = (float)N_EXP * loss;
    }
}

// ---------------------------------------------------------------------------
extern "C" void kernel_launch(void* const* d_in, const int* in_sizes, int n_in,
                              void* d_out, int out_size)
{
    const float* vis   = (const float*)d_in[0];
    const float* lang  = (const float*)d_in[1];
    const float* state = (const float*)d_in[2];
    const float* Wf    = (const float*)d_in[3];
    const float* bf    = (const float*)d_in[4];
    const float* gf    = (const float*)d_in[5];
    const float* bfln  = (const float*)d_in[6];
    const float* Wg    = (const float*)d_in[7];
    const float* W1    = (const float*)d_in[8];
    const float* b1    = (const float*)d_in[9];
    const float* W2    = (const float*)d_in[10];
    const float* b2    = (const float*)d_in[11];
    const float* W3    = (const float*)d_in[12];
    const float* b3    = (const float*)d_in[13];
    const float* eg    = (const float*)d_in[14];
    const float* eb    = (const float*)d_in[15];
    float* out = (float*)d_out;

    cudaFuncSetAttribute(expert_kernel,
                         cudaFuncAttributeMaxDynamicSharedMemorySize, 196608);

    fusion_kernel<<<B_TOK / 64, 256>>>(vis, lang, state, Wf, bf, gf, bfln);
    gate_kernel<<<B_TOK / 8, 256>>>(Wg);
    offsets_kernel<<<1, 256>>>();
    scatter_kernel<<<64, 256>>>();
    loss_kernel<<<1, 256>>>(out, out_size);          // before expert: ncu -s 5 lands on expert
    expert_kernel<<<MAXB, 256, 196608>>>(W1, b1, W2, b2, W3, b3, eg, eb, out);
}

// round 6
// speedup vs baseline: 1.8391x; 1.0401x over previous
#include <cuda_runtime.h>
#include <cuda_bf16.h>
#include <math.h>

// Problem constants
#define B_TOK   16384
#define D_VIS   768
#define D_LANG  768
#define D_STATE 64
#define D_IN    1600
#define D_MODEL 256
#define N_EXP   4
#define TOPK    2
#define MAXB    518           // max expert blocks after per-bucket padding
#define PERM_N  (MAXB * 32)   // 16576

typedef unsigned long long u64;

// ---------------------------------------------------------------------------
// Scratch
// ---------------------------------------------------------------------------
__device__ float g_x[B_TOK * D_MODEL];
__device__ int   g_topidx[B_TOK];             // i0 | (i1<<8)
__device__ float g_topw[B_TOK * 2];
__device__ float g_partial[2048 * 8];
__device__ int   g_bcount[8];                 // per-pair-bucket counts
__device__ int   g_off[8];                    // padded bucket offsets [0..6]
__device__ int   g_pair_slot[B_TOK];          // pid | (slot<<4)
__device__ int   g_perm[PERM_N];              // token index or -1
__device__ unsigned g_done;                   // gate completion ticket

__device__ __forceinline__ float gelu_exact(float v) {
    return 0.5f * v * (1.f + erff(v * 0.70710678118654752f));
}

// ---- packed fp32 helpers ---------------------------------------------------
__device__ __forceinline__ u64 pack2(float x, float y) {
    u64 r; asm("mov.b64 %0, {%1, %2};" : "=l"(r) : "f"(x), "f"(y)); return r;
}
__device__ __forceinline__ void fma2(u64& d, u64 a, u64 b) {
    asm("fma.rn.f32x2 %0, %1, %2, %0;" : "+l"(d) : "l"(a), "l"(b));
}
__device__ __forceinline__ float2 unpack2(u64 v) {
    float2 r; asm("mov.b64 {%0, %1}, %2;" : "=f"(r.x), "=f"(r.y) : "l"(v)); return r;
}

// ---- cp.async helpers ------------------------------------------------------
__device__ __forceinline__ void cp16(unsigned saddr, const void* g) {
    asm volatile("cp.async.cg.shared.global [%0], [%1], 16;" :: "r"(saddr), "l"(g));
}
__device__ __forceinline__ void cp_commit() { asm volatile("cp.async.commit_group;"); }
__device__ __forceinline__ void cp_wait1()  { asm volatile("cp.async.wait_group 1;"); }
__device__ __forceinline__ void cp_wait0()  { asm volatile("cp.async.wait_group 0;"); }

// stage = 8192 floats (32KB), 2048 float4, 8 per thread
__device__ __forceinline__ void stage_issue(unsigned sbuf, const float* gsrc, int tid) {
#pragma unroll
    for (int i = 0; i < 8; i++) {
        int idx = tid + i * 256;
        cp16(sbuf + idx * 16, (const void*)(gsrc + idx * 4));
    }
    cp_commit();
}

// ---------------------------------------------------------------------------
// Kernel A: x = gelu(LN(concat @ Wf + bf))   (64x256 tile per block)
// cp.async double-buffered A (64x32) and B (32x256) tiles, k-tile=32.
// Dynamic SMEM: 2*(2048 + 8192) floats = 80KB; 2 CTAs/SM.
// ---------------------------------------------------------------------------
extern __shared__ float smemA[];

__global__ __launch_bounds__(256, 2) void fusion_kernel(
    const float* __restrict__ vis, const float* __restrict__ lang,
    const float* __restrict__ state, const float* __restrict__ Wf,
    const float* __restrict__ bf, const float* __restrict__ gf,
    const float* __restrict__ bfln)
{
    float* As = smemA;            // 2 x [64][32]
    float* Bs = smemA + 4096;     // 2 x [32][256]

    const int tid = threadIdx.x;
    const int tx = tid & 31;
    const int ty = tid >> 5;
    const int row0 = blockIdx.x * 64;

    if (blockIdx.x == 0 && tid < 8) g_bcount[tid] = 0;   // reset for gate atomics
    if (blockIdx.x < 65) {                               // init perm for scatter
        int i = blockIdx.x * 256 + tid;
        if (i < PERM_N) g_perm[i] = -1;
    }

    const unsigned au = (unsigned)__cvta_generic_to_shared(As);
    const unsigned bu = (unsigned)__cvta_generic_to_shared(Bs);

    u64 acc[8][4];
#pragma unroll
    for (int i = 0; i < 8; i++)
#pragma unroll
        for (int j = 0; j < 4; j++) acc[i][j] = 0ull;

    // tile t: k range [32t, 32t+32). 768 and 1536 are multiples of 32,
    // so no tile straddles a source boundary.
    auto issue_tile = [&](int t, int buf) {
        const float* srcp; int stride, col0;
        if (t < 24)      { srcp = vis;   stride = D_VIS;   col0 = t * 32; }
        else if (t < 48) { srcp = lang;  stride = D_LANG;  col0 = t * 32 - 768; }
        else             { srcp = state; stride = D_STATE; col0 = t * 32 - 1536; }
        unsigned ab = au + buf * 8192;     // 2048 floats per A buffer
#pragma unroll
        for (int i = 0; i < 2; i++) {      // 512 float4, 2 per thread
            int idx = tid + i * 256;
            int r = idx >> 3, c4 = (idx & 7) << 2;
            cp16(ab + idx * 16, srcp + (size_t)(row0 + r) * stride + col0 + c4);
        }
        unsigned bb = bu + buf * 32768;    // 8192 floats per B buffer
#pragma unroll
        for (int i = 0; i < 8; i++) {      // 2048 float4, 8 per thread
            int idx = tid + i * 256;
            int r = idx >> 6, c = (idx & 63) << 2;
            cp16(bb + idx * 16, Wf + (size_t)(t * 32 + r) * 256 + c);
        }
        cp_commit();
    };

    issue_tile(0, 0);
#pragma unroll 1
    for (int s = 0; s < 50; s++) {
        if (s + 1 < 50) { issue_tile(s + 1, (s + 1) & 1); cp_wait1(); }
        else cp_wait0();
        __syncthreads();
        const float* Ab = As + (s & 1) * 2048;
        const float* Bb = Bs + (s & 1) * 8192;
#pragma unroll 4
        for (int k2 = 0; k2 < 16; k2++) {
            u64 a2[8];
#pragma unroll
            for (int i = 0; i < 8; i++)
                a2[i] = *(const u64*)&Ab[(ty * 8 + i) * 32 + 2 * k2];
            u64 bA[4], bB[4];
#pragma unroll
            for (int j = 0; j < 4; j++) {
                bA[j] = *(const u64*)&Bb[(2 * k2)     * 256 + 2 * tx + 64 * j];
                bB[j] = *(const u64*)&Bb[(2 * k2 + 1) * 256 + 2 * tx + 64 * j];
            }
#pragma unroll
            for (int i = 0; i < 8; i++) {
                float2 a = unpack2(a2[i]);
                u64 ap0 = pack2(a.x, a.x), ap1 = pack2(a.y, a.y);
#pragma unroll
                for (int j = 0; j < 4; j++) {
                    fma2(acc[i][j], ap0, bA[j]);
                    fma2(acc[i][j], ap1, bB[j]);
                }
            }
        }
        __syncthreads();
    }

    // Epilogue: +bias, LayerNorm per row (warp holds full row), GELU, store
    float2 bfv[4], gv[4], bv[4];
#pragma unroll
    for (int j = 0; j < 4; j++) {
        int n = 2 * tx + 64 * j;
        bfv[j] = *(const float2*)(bf + n);
        gv[j]  = *(const float2*)(gf + n);
        bv[j]  = *(const float2*)(bfln + n);
    }
#pragma unroll
    for (int i = 0; i < 8; i++) {
        int row = row0 + ty * 8 + i;
        float v[8];
        float s = 0.f;
#pragma unroll
        for (int j = 0; j < 4; j++) {
            float2 p = unpack2(acc[i][j]);
            v[2 * j]     = p.x + bfv[j].x;
            v[2 * j + 1] = p.y + bfv[j].y;
            s += v[2 * j] + v[2 * j + 1];
        }
#pragma unroll
        for (int off = 16; off; off >>= 1) s += __shfl_xor_sync(0xffffffffu, s, off);
        float mu = s * (1.f / 256.f);
        float vs = 0.f;
#pragma unroll
        for (int j = 0; j < 8; j++) { float d = v[j] - mu; vs += d * d; }
#pragma unroll
        for (int off = 16; off; off >>= 1) vs += __shfl_xor_sync(0xffffffffu, vs, off);
        float rstd = rsqrtf(vs * (1.f / 256.f) + 1e-5f);
#pragma unroll
        for (int j = 0; j < 4; j++) {
            float y0 = gv[j].x * (v[2 * j]     - mu) * rstd + bv[j].x;
            float y1 = gv[j].y * (v[2 * j + 1] - mu) * rstd + bv[j].y;
            *(float2*)&g_x[(size_t)row * D_MODEL + 2 * tx + 64 * j] =
                make_float2(gelu_exact(y0), gelu_exact(y1));
        }
    }
}

// ---------------------------------------------------------------------------
// Kernel B: gate + top-2 + pair-bucket slot assignment + lb-loss partials.
// The LAST block to finish also computes the padded bucket offsets (g_off),
// removing the separate offsets kernel.
// ---------------------------------------------------------------------------
__global__ __launch_bounds__(256) void gate_kernel(const float* __restrict__ Wg)
{
    const int tid = threadIdx.x, lane = tid & 31, w = tid >> 5;
    const int t = blockIdx.x * 8 + w;

    float p0 = 0.f, p1 = 0.f, p2 = 0.f, p3 = 0.f;
    const float* xr = g_x + (size_t)t * D_MODEL;
#pragma unroll
    for (int j = 0; j < 8; j++) {
        int c = lane + 32 * j;
        float xv = xr[c];
        float4 wg = *(const float4*)(Wg + c * 4);
        p0 = fmaf(xv, wg.x, p0); p1 = fmaf(xv, wg.y, p1);
        p2 = fmaf(xv, wg.z, p2); p3 = fmaf(xv, wg.w, p3);
    }
#pragma unroll
    for (int off = 16; off; off >>= 1) {
        p0 += __shfl_xor_sync(0xffffffffu, p0, off);
        p1 += __shfl_xor_sync(0xffffffffu, p1, off);
        p2 += __shfl_xor_sync(0xffffffffu, p2, off);
        p3 += __shfl_xor_sync(0xffffffffu, p3, off);
    }

    __shared__ float sprob[8][4];
    __shared__ float scnt[8][4];
    if (lane == 0) {
        float l[4] = {p0, p1, p2, p3};
        float mx = fmaxf(fmaxf(l[0], l[1]), fmaxf(l[2], l[3]));
        float e[4], se = 0.f;
#pragma unroll
        for (int i = 0; i < 4; i++) { e[i] = expf(l[i] - mx); se += e[i]; }
        float inv = 1.f / se;
#pragma unroll
        for (int i = 0; i < 4; i++) sprob[w][i] = e[i] * inv;

        int i0 = 0;
#pragma unroll
        for (int i = 1; i < 4; i++) if (l[i] > l[i0]) i0 = i;
        int i1 = -1;
#pragma unroll
        for (int i = 0; i < 4; i++) {
            if (i == i0) continue;
            if (i1 < 0 || l[i] > l[i1]) i1 = i;
        }
        float w0 = 1.f / (1.f + expf(l[i1] - l[i0]));
        g_topidx[t] = i0 | (i1 << 8);
        g_topw[2 * t]     = w0;
        g_topw[2 * t + 1] = 1.f - w0;
#pragma unroll
        for (int i = 0; i < 4; i++) scnt[w][i] = (i == i0 || i == i1) ? 1.f : 0.f;

        // unordered pair bucket (triangular index, E=4):
        // (0,1)=0 (0,2)=1 (0,3)=2 (1,2)=3 (1,3)=4 (2,3)=5
        int a = min(i0, i1), b = max(i0, i1);
        int pid = (a * (7 - a)) / 2 + (b - a - 1);
        int slot = atomicAdd(&g_bcount[pid], 1);
        g_pair_slot[t] = pid | (slot << 4);
    }
    __syncthreads();
    if (tid < 4) {
        float s = 0.f;
        for (int ww = 0; ww < 8; ww++) s += sprob[ww][tid];
        g_partial[blockIdx.x * 8 + tid] = s;
    } else if (tid < 8) {
        int e = tid - 4;
        float s = 0.f;
        for (int ww = 0; ww < 8; ww++) s += scnt[ww][e];
        g_partial[blockIdx.x * 8 + tid] = s;
    }
    // last-block ticket: compute padded bucket offsets
    __syncthreads();
    if (tid == 0) {
        __threadfence();
        unsigned ticket = atomicAdd(&g_done, 1u);
        if (ticket == gridDim.x - 1) {
            g_done = 0;                     // reset for next graph replay
            __threadfence();
            int o = 0;
#pragma unroll
            for (int p = 0; p < 6; p++) {
                g_off[p] = o;
                o += (g_bcount[p] + 31) & ~31;
            }
            g_off[6] = o;
        }
    }
}

// ---------------------------------------------------------------------------
// Kernel B3: scatter tokens into bucketed permutation
// ---------------------------------------------------------------------------
__global__ __launch_bounds__(256) void scatter_kernel()
{
    int t = blockIdx.x * 256 + threadIdx.x;
    if (t < B_TOK) {
        int ps = g_pair_slot[t];
        int pid = ps & 15, slot = ps >> 4;
        g_perm[g_off[pid] + slot] = t;
    }
}

// ---------------------------------------------------------------------------
// Kernel C: bucketed expert chain — 32 tokens/block, only the 2 selected
// experts. 8-row x {4,2}-pair register tiles; cp.async double-buffered
// weight staging (2x32KB). Dynamic SMEM = 192KB.
// ---------------------------------------------------------------------------
extern __shared__ float smemC[];

__global__ __launch_bounds__(256, 1) void expert_kernel(
    const float* __restrict__ W1, const float* __restrict__ b1,
    const float* __restrict__ W2, const float* __restrict__ b2,
    const float* __restrict__ W3, const float* __restrict__ b3,
    const float* __restrict__ eg, const float* __restrict__ eb,
    float* __restrict__ out)
{
    float* x_s  = smemC;            // [32][256]  32KB
    float* h1_s = smemC + 8192;     // [32][512]  64KB
    float* h2_s = smemC + 24576;    // [32][256]  32KB
    float* w_s  = smemC + 32768;    // 2 x 8192   64KB
    __shared__ int   s_tok[32];
    __shared__ float ln_s[32][4];

    const int tid = threadIdx.x, tx = tid & 31, wid = tid >> 5;
    const int rowgrp = wid >> 1, colgrp = wid & 1;
    const int rowbase = rowgrp * 8;
    const int base = blockIdx.x * 32;

    int off6 = g_off[6];
    if (base >= off6) return;
    int pid = 0;
#pragma unroll
    for (int p = 0; p < 5; p++) if (base >= g_off[p + 1]) pid = p + 1;
    const int pe0[6] = {0, 0, 0, 1, 1, 2};
    const int pe1[6] = {1, 2, 3, 2, 3, 3};
    const int e0 = pe0[pid], e1 = pe1[pid];

    if (tid < 32) s_tok[tid] = g_perm[base + tid];
    __syncthreads();

    // gather x tile
#pragma unroll
    for (int i = 0; i < 8; i++) {
        int idx = tid + i * 256;
        int r = idx >> 6, c = (idx & 63) << 2;
        int tk = s_tok[r]; if (tk < 0) tk = 0;
        *(float4*)&x_s[r * 256 + c] = *(const float4*)(g_x + (size_t)tk * 256 + c);
    }

    float out_acc[8][4];
#pragma unroll
    for (int jm = 0; jm < 8; jm++)
#pragma unroll
        for (int j = 0; j < 4; j++) out_acc[jm][j] = 0.f;
    __syncthreads();

    const unsigned wu = (unsigned)__cvta_generic_to_shared(w_s);
    const int cb1 = colgrp * 256;   // GEMM1 column base (N=512)
    const int cb2 = colgrp * 128;   // GEMM2/3 column base (N=256)

#pragma unroll 1
    for (int ei = 0; ei < 2; ei++) {
        const int e = ei ? e1 : e0;

        // ================= GEMM1: h1 = gelu(x @ W1[e] + b1)  K=256, N=512
        {
            const float* W1e = W1 + (size_t)e * 256 * 512;
            u64 acc1[8][4];
#pragma unroll
            for (int jm = 0; jm < 8; jm++)
#pragma unroll
                for (int p = 0; p < 4; p++) acc1[jm][p] = 0ull;

            stage_issue(wu, W1e, tid);                       // stage0 -> buf0
#pragma unroll 1
            for (int s = 0; s < 16; s++) {
                if (s + 1 < 16) {
                    stage_issue(wu + ((s + 1) & 1) * 32768, W1e + (size_t)(s + 1) * 16 * 512, tid);
                    cp_wait1();
                } else cp_wait0();
                __syncthreads();
                const float* wb = w_s + (s & 1) * 8192;
                const int kk = s * 16;
#pragma unroll 4
                for (int k2 = 0; k2 < 8; k2++) {
                    u64 a2[8];
#pragma unroll
                    for (int jm = 0; jm < 8; jm++)
                        a2[jm] = *(const u64*)&x_s[(rowbase + jm) * 256 + kk + 2 * k2];
                    u64 wA[4], wB[4];
#pragma unroll
                    for (int p = 0; p < 4; p++) {
                        wA[p] = *(const u64*)&wb[(2 * k2)     * 512 + cb1 + 2 * tx + 64 * p];
                        wB[p] = *(const u64*)&wb[(2 * k2 + 1) * 512 + cb1 + 2 * tx + 64 * p];
                    }
#pragma unroll
                    for (int jm = 0; jm < 8; jm++) {
                        float2 a = unpack2(a2[jm]);
                        u64 ap0 = pack2(a.x, a.x), ap1 = pack2(a.y, a.y);
#pragma unroll
                        for (int p = 0; p < 4; p++) {
                            fma2(acc1[jm][p], ap0, wA[p]);
                            fma2(acc1[jm][p], ap1, wB[p]);
                        }
                    }
                }
                __syncthreads();
            }
#pragma unroll
            for (int p = 0; p < 4; p++) {
                int n = cb1 + 2 * tx + 64 * p;
                float2 bb = *(const float2*)(b1 + e * 512 + n);
#pragma unroll
                for (int jm = 0; jm < 8; jm++) {
                    float2 v = unpack2(acc1[jm][p]);
                    *(float2*)&h1_s[(rowbase + jm) * 512 + n] =
                        make_float2(gelu_exact(v.x + bb.x), gelu_exact(v.y + bb.y));
                }
            }
        }

        // ================= GEMM2: h2 = gelu(h1 @ W2[e] + b2)  K=512, N=256
        {
            const float* W2e = W2 + (size_t)e * 512 * 256;
            u64 acc2[8][2];
#pragma unroll
            for (int jm = 0; jm < 8; jm++)
#pragma unroll
                for (int p = 0; p < 2; p++) acc2[jm][p] = 0ull;

            stage_issue(wu, W2e, tid);
#pragma unroll 1
            for (int s = 0; s < 16; s++) {
                if (s + 1 < 16) {
                    stage_issue(wu + ((s + 1) & 1) * 32768, W2e + (size_t)(s + 1) * 32 * 256, tid);
                    cp_wait1();
                } else cp_wait0();
                __syncthreads();   // also orders h1_s writes (iter 0)
                const float* wb = w_s + (s & 1) * 8192;
                const int kk = s * 32;
#pragma unroll 4
                for (int k2 = 0; k2 < 16; k2++) {
                    u64 a2[8];
#pragma unroll
                    for (int jm = 0; jm < 8; jm++)
                        a2[jm] = *(const u64*)&h1_s[(rowbase + jm) * 512 + kk + 2 * k2];
                    u64 wA[2], wB[2];
#pragma unroll
                    for (int p = 0; p < 2; p++) {
                        wA[p] = *(const u64*)&wb[(2 * k2)     * 256 + cb2 + 2 * tx + 64 * p];
                        wB[p] = *(const u64*)&wb[(2 * k2 + 1) * 256 + cb2 + 2 * tx + 64 * p];
                    }
#pragma unroll
                    for (int jm = 0; jm < 8; jm++) {
                        float2 a = unpack2(a2[jm]);
                        u64 ap0 = pack2(a.x, a.x), ap1 = pack2(a.y, a.y);
#pragma unroll
                        for (int p = 0; p < 2; p++) {
                            fma2(acc2[jm][p], ap0, wA[p]);
                            fma2(acc2[jm][p], ap1, wB[p]);
                        }
                    }
                }
                __syncthreads();
            }
#pragma unroll
            for (int p = 0; p < 2; p++) {
                int n = cb2 + 2 * tx + 64 * p;
                float2 bb = *(const float2*)(b2 + e * 256 + n);
#pragma unroll
                for (int jm = 0; jm < 8; jm++) {
                    float2 v = unpack2(acc2[jm][p]);
                    *(float2*)&h2_s[(rowbase + jm) * 256 + n] =
                        make_float2(gelu_exact(v.x + bb.x), gelu_exact(v.y + bb.y));
                }
            }
        }

        // ================= GEMM3: h3 = h2 @ W3[e] + b3  K=256, N=256
        u64 acc3[8][2];
#pragma unroll
        for (int jm = 0; jm < 8; jm++)
#pragma unroll
            for (int p = 0; p < 2; p++) acc3[jm][p] = 0ull;
        {
            const float* W3e = W3 + (size_t)e * 256 * 256;
            stage_issue(wu, W3e, tid);
#pragma unroll 1
            for (int s = 0; s < 8; s++) {
                if (s + 1 < 8) {
                    stage_issue(wu + ((s + 1) & 1) * 32768, W3e + (size_t)(s + 1) * 32 * 256, tid);
                    cp_wait1();
                } else cp_wait0();
                __syncthreads();   // also orders h2_s writes (iter 0)
                const float* wb = w_s + (s & 1) * 8192;
                const int kk = s * 32;
#pragma unroll 4
                for (int k2 = 0; k2 < 16; k2++) {
                    u64 a2[8];
#pragma unroll
                    for (int jm = 0; jm < 8; jm++)
                        a2[jm] = *(const u64*)&h2_s[(rowbase + jm) * 256 + kk + 2 * k2];
                    u64 wA[2], wB[2];
#pragma unroll
                    for (int p = 0; p < 2; p++) {
                        wA[p] = *(const u64*)&wb[(2 * k2)     * 256 + cb2 + 2 * tx + 64 * p];
                        wB[p] = *(const u64*)&wb[(2 * k2 + 1) * 256 + cb2 + 2 * tx + 64 * p];
                    }
#pragma unroll
                    for (int jm = 0; jm < 8; jm++) {
                        float2 a = unpack2(a2[jm]);
                        u64 ap0 = pack2(a.x, a.x), ap1 = pack2(a.y, a.y);
#pragma unroll
                        for (int p = 0; p < 2; p++) {
                            fma2(acc3[jm][p], ap0, wA[p]);
                            fma2(acc3[jm][p], ap1, wB[p]);
                        }
                    }
                }
                __syncthreads();
            }
        }

        // ================= Epilogue: LN(x + h3), weighted accumulate
        float2 b3v[2], egv[2], ebv[2];
#pragma unroll
        for (int p = 0; p < 2; p++) {
            int n = cb2 + 2 * tx + 64 * p;
            b3v[p] = *(const float2*)(b3 + e * 256 + n);
            egv[p] = *(const float2*)(eg + e * 256 + n);
            ebv[p] = *(const float2*)(eb + e * 256 + n);
        }
        // pass 1: per-row partial sums (row spans 2 warps -> smem combine)
#pragma unroll
        for (int jm = 0; jm < 8; jm++) {
            int row = rowbase + jm;
            float2 h0 = unpack2(acc3[jm][0]), h1v = unpack2(acc3[jm][1]);
            float2 x0 = *(const float2*)&x_s[row * 256 + cb2 + 2 * tx];
            float2 x1 = *(const float2*)&x_s[row * 256 + cb2 + 2 * tx + 64];
            float v0 = h0.x + b3v[0].x + x0.x;
            float v1 = h0.y + b3v[0].y + x0.y;
            float v2 = h1v.x + b3v[1].x + x1.x;
            float v3 = h1v.y + b3v[1].y + x1.y;
            float s4 = v0 + v1 + v2 + v3;
            float ss = v0 * v0 + v1 * v1 + v2 * v2 + v3 * v3;
#pragma unroll
            for (int o = 16; o; o >>= 1) {
                s4 += __shfl_xor_sync(0xffffffffu, s4, o);
                ss += __shfl_xor_sync(0xffffffffu, ss, o);
            }
            if (tx == 0) { ln_s[row][colgrp * 2] = s4; ln_s[row][colgrp * 2 + 1] = ss; }
        }
        __syncthreads();
        // pass 2: normalize + accumulate
#pragma unroll
        for (int jm = 0; jm < 8; jm++) {
            int row = rowbase + jm;
            int tk = s_tok[row];
            float wsel = 0.f;
            if (tk >= 0) {
                int ip = g_topidx[tk];
                wsel = (e == (ip & 0xff)) ? g_topw[2 * tk] : g_topw[2 * tk + 1];
            }
            float sm = ln_s[row][0] + ln_s[row][2];
            float sq = ln_s[row][1] + ln_s[row][3];
            float mu = sm * (1.f / 256.f);
            float var = sq * (1.f / 256.f) - mu * mu;
            float rstd = rsqrtf(var + 1e-5f);
            float2 h0 = unpack2(acc3[jm][0]), h1v = unpack2(acc3[jm][1]);
            float2 x0 = *(const float2*)&x_s[row * 256 + cb2 + 2 * tx];
            float2 x1 = *(const float2*)&x_s[row * 256 + cb2 + 2 * tx + 64];
            float v[4] = { h0.x + b3v[0].x + x0.x, h0.y + b3v[0].y + x0.y,
                           h1v.x + b3v[1].x + x1.x, h1v.y + b3v[1].y + x1.y };
            float gvv[4] = { egv[0].x, egv[0].y, egv[1].x, egv[1].y };
            float bvv[4] = { ebv[0].x, ebv[0].y, ebv[1].x, ebv[1].y };
#pragma unroll
            for (int j = 0; j < 4; j++) {
                float y = gvv[j] * (v[j] - mu) * rstd + bvv[j];
                out_acc[jm][j] = fmaf(wsel, y, out_acc[jm][j]);
            }
        }
        __syncthreads();
    }

    // store (each valid token written exactly once)
#pragma unroll
    for (int jm = 0; jm < 8; jm++) {
        int row = rowbase + jm;
        int tk = s_tok[row];
        if (tk >= 0) {
            *(float2*)&out[(size_t)tk * 256 + cb2 + 2 * tx] =
                make_float2(out_acc[jm][0], out_acc[jm][1]);
            *(float2*)&out[(size_t)tk * 256 + cb2 + 2 * tx + 64] =
                make_float2(out_acc[jm][2], out_acc[jm][3]);
        }
    }
}

// ---------------------------------------------------------------------------
// Kernel D: deterministic final reduction for load-balance loss
// ---------------------------------------------------------------------------
__global__ __launch_bounds__(256) void loss_kernel(float* __restrict__ out, int out_size)
{
    __shared__ float sh[256];
    __shared__ float totals[8];
    int tid = threadIdx.x;
    float acc[8];
#pragma unroll
    for (int f = 0; f < 8; f++) acc[f] = 0.f;
    for (int i = tid; i < 2048; i += 256) {
#pragma unroll
        for (int f = 0; f < 8; f++) acc[f] += g_partial[i * 8 + f];
    }
    for (int f = 0; f < 8; f++) {
        sh[tid] = acc[f];
        __syncthreads();
        for (int s = 128; s > 0; s >>= 1) {
            if (tid < s) sh[tid] += sh[tid + s];
            __syncthreads();
        }
        if (tid == 0) totals[f] = sh[0];
        __syncthreads();
    }
    if (tid == 0 && out_size > B_TOK * D_MODEL) {
        float loss = 0.f;
#pragma unroll
        for (int i = 0; i < 4; i++) {
            float f_i = totals[4 + i] / (float)(B_TOK * TOPK);
            float pm  = totals[i] / (float)B_TOK;
            loss += f_i * pm;
        }
        out[B_TOK * D_MODEL] = (float)N_EXP * loss;
    }
}

// ---------------------------------------------------------------------------
extern "C" void kernel_launch(void* const* d_in, const int* in_sizes, int n_in,
                              void* d_out, int out_size)
{
    const float* vis   = (const float*)d_in[0];
    const float* lang  = (const float*)d_in[1];
    const float* state = (const float*)d_in[2];
    const float* Wf    = (const float*)d_in[3];
    const float* bf    = (const float*)d_in[4];
    const float* gf    = (const float*)d_in[5];
    const float* bfln  = (const float*)d_in[6];
    const float* Wg    = (const float*)d_in[7];
    const float* W1    = (const float*)d_in[8];
    const float* b1    = (const float*)d_in[9];
    const float* W2    = (const float*)d_in[10];
    const float* b2    = (const float*)d_in[11];
    const float* W3    = (const float*)d_in[12];
    const float* b3    = (const float*)d_in[13];
    const float* eg    = (const float*)d_in[14];
    const float* eb    = (const float*)d_in[15];
    float* out = (float*)d_out;

    cudaFuncSetAttribute(fusion_kernel,
                         cudaFuncAttributeMaxDynamicSharedMemorySize, 81920);
    cudaFuncSetAttribute(expert_kernel,
                         cudaFuncAttributeMaxDynamicSharedMemorySize, 196608);

    fusion_kernel<<<B_TOK / 64, 256, 81920>>>(vis, lang, state, Wf, bf, gf, bfln);
    gate_kernel<<<B_TOK / 8, 256>>>(Wg);               // includes offsets (last block)
    scatter_kernel<<<64, 256>>>();
    expert_kernel<<<MAXB, 256, 196608>>>(W1, b1, W2, b2, W3, b3, eg, eb, out);  // 4th -> profiled
    loss_kernel<<<1, 256>>>(out, out_size);
}